// round 3
// baseline (speedup 1.0000x reference)
#include <cuda_runtime.h>
#include <math.h>

#define NN    10000
#define NE    160000
#define HH    128
#define NRBF  32
#define NLAT  64
#define NGR   128
#define CUTR  5.0f
#define EPSF  1e-8f

// ---------------- device scratch (static allocation; allowed) ----------------
__device__ __align__(16) float g_x[NN * HH];
__device__ __align__(16) float g_dx[NN * HH];
__device__ __align__(16) float g_vec[NN * 3 * HH];
__device__ __align__(16) float g_vmix[NN * 3 * HH];
__device__ __align__(16) float g_vnorm[NN * HH];
__device__ __align__(16) float g_rbf[NE * NRBF];
__device__ __align__(16) float g_dirn[NE * 4];      // (ux,uy,uz,r)
__device__ __align__(16) float g_filt[NE * HH];
__device__ __align__(16) float g_phi[NE * HH];
__device__ __align__(16) float g_pooled[NGR * 65];

__device__ __forceinline__ void fma4(float4& acc, float a, const float4& b) {
    acc.x += a * b.x; acc.y += a * b.y; acc.z += a * b.z; acc.w += a * b.w;
}
__device__ __forceinline__ float4 silu4(const float4& v) {
    float4 r;
    r.x = v.x / (1.f + __expf(-v.x));
    r.y = v.y / (1.f + __expf(-v.y));
    r.z = v.z / (1.f + __expf(-v.z));
    r.w = v.w / (1.f + __expf(-v.w));
    return r;
}
__device__ __forceinline__ void atomicAdd4(float* p, const float4& v) {
#if __CUDA_ARCH__ >= 900
    atomicAdd((float4*)p, v);
#else
    atomicAdd(p + 0, v.x); atomicAdd(p + 1, v.y);
    atomicAdd(p + 2, v.z); atomicAdd(p + 3, v.w);
#endif
}

// ---------------- init / zero ----------------
__global__ void k_zero_init() {
    int stride = gridDim.x * blockDim.x;
    for (int i = blockIdx.x * blockDim.x + threadIdx.x; i < NN * 3 * HH; i += stride) g_vec[i] = 0.f;
    for (int i = blockIdx.x * blockDim.x + threadIdx.x; i < NGR * 65; i += stride) g_pooled[i] = 0.f;
}
__global__ void k_zero_dx() {
    int stride = gridDim.x * blockDim.x;
    for (int i = blockIdx.x * blockDim.x + threadIdx.x; i < NN * HH; i += stride) g_dx[i] = 0.f;
}
__global__ void k_init_x(const int* __restrict__ z, const float* __restrict__ emb) {
    int stride = gridDim.x * blockDim.x;
    for (int i = blockIdx.x * blockDim.x + threadIdx.x; i < NN * HH; i += stride) {
        int n = i >> 7, h = i & 127;
        g_x[i] = emb[z[n] * HH + h];
    }
}

// ---------------- edge geometry + RBF ----------------
__global__ void k_edgeprep(const int* __restrict__ ei, const float* __restrict__ pos) {
    int e = blockIdx.x * blockDim.x + threadIdx.x;
    if (e >= NE) return;
    int s = ei[e], t = ei[NE + e];
    float dx = pos[t * 3 + 0] - pos[s * 3 + 0];
    float dy = pos[t * 3 + 1] - pos[s * 3 + 1];
    float dz = pos[t * 3 + 2] - pos[s * 3 + 2];
    float r = sqrtf(dx * dx + dy * dy + dz * dz + EPSF);
    float inv = 1.f / r;
    ((float4*)g_dirn)[e] = make_float4(dx * inv, dy * inv, dz * inv, r);

    const float m0 = expf(-CUTR);
    const float step = (1.f - m0) / (NRBF - 1);
    const float bl = (2.f / NRBF) * (1.f - m0);
    const float beta = 1.f / (bl * bl);
    float cutv = (r < CUTR) ? 0.5f * (cosf(3.14159265358979323846f * r / CUTR) + 1.f) : 0.f;
    float er = expf(-r);
#pragma unroll
    for (int i = 0; i < NRBF; i++) {
        float m = m0 + step * (float)i;
        float d = er - m;
        g_rbf[e * NRBF + i] = cutv * expf(-beta * d * d);
    }
}

// ---------------- fused filt + phi GEMM + dx scatter ----------------
// smem: Wrbf[32x128] + W1[128x128] + rowbuf[8 warps][512]
#define SMEM_EDGEPHI ((32 * HH + HH * HH + 8 * 512) * 4)
__global__ void k_edge_phi(const int* __restrict__ ei,
                           const float* __restrict__ Wrbf,
                           const float* __restrict__ W1) {
    extern __shared__ float sm[];
    float* WrbfSh = sm;
    float* W1sh = sm + 32 * HH;
    float* rowAll = W1sh + HH * HH;
    int tid = threadIdx.x, warp = tid >> 5, lane = tid & 31;
    for (int i = tid; i < 32 * HH; i += blockDim.x) WrbfSh[i] = Wrbf[i];
    for (int i = tid; i < HH * HH; i += blockDim.x) W1sh[i] = W1[i];
    __syncthreads();
    float* row = rowAll + warp * 512;
    const float4* W1sh4 = (const float4*)W1sh;
    const float4* WrbfSh4 = (const float4*)WrbfSh;

    int nGroups = NE / 4;
    int stride = gridDim.x * 8;
    for (int g = blockIdx.x * 8 + warp; g < nGroups; g += stride) {
        int e0 = g * 4;
        int srcs[4], dsts[4];
#pragma unroll
        for (int i = 0; i < 4; i++) {
            int e = e0 + i;
            srcs[i] = ei[e]; dsts[i] = ei[NE + e];
            row[i * 32 + lane] = g_rbf[e * 32 + lane];
        }
        __syncwarp();
        float4 f[4];
#pragma unroll
        for (int i = 0; i < 4; i++) f[i] = make_float4(0.f, 0.f, 0.f, 0.f);
#pragma unroll 4
        for (int k = 0; k < 32; k++) {
            float4 wv = WrbfSh4[k * 32 + lane];
#pragma unroll
            for (int i = 0; i < 4; i++) fma4(f[i], row[i * 32 + k], wv);
        }
        __syncwarp();
#pragma unroll
        for (int i = 0; i < 4; i++) {
            int e = e0 + i;
            float4 xs = *(const float4*)&g_x[srcs[i] * HH + lane * 4];
            ((float4*)&g_filt[e * HH])[lane] = f[i];
            float4 u = make_float4(xs.x * f[i].x, xs.y * f[i].y, xs.z * f[i].z, xs.w * f[i].w);
            ((float4*)row)[i * 32 + lane] = u;
        }
        __syncwarp();
        float4 acc[4];
#pragma unroll
        for (int i = 0; i < 4; i++) acc[i] = make_float4(0.f, 0.f, 0.f, 0.f);
#pragma unroll 4
        for (int k = 0; k < HH; k++) {
            float4 b4 = W1sh4[k * 32 + lane];
#pragma unroll
            for (int i = 0; i < 4; i++) fma4(acc[i], row[i * HH + k], b4);
        }
#pragma unroll
        for (int i = 0; i < 4; i++) {
            int e = e0 + i;
            float4 p = silu4(acc[i]);
            ((float4*)&g_phi[e * HH])[lane] = p;
            atomicAdd4(&g_dx[dsts[i] * HH + lane * 4], p);
        }
        __syncwarp();
    }
}

// ---------------- vmix = vec @ Wv (N*3 rows) ----------------
#define SMEM_GEMM ((HH * HH + 8 * 512) * 4)
__global__ void k_vmix(const float* __restrict__ Wv) {
    extern __shared__ float sm[];
    float* Bsh = sm;
    float* rowAll = sm + HH * HH;
    int tid = threadIdx.x, warp = tid >> 5, lane = tid & 31;
    for (int i = tid; i < HH * HH; i += blockDim.x) Bsh[i] = Wv[i];
    __syncthreads();
    float* row = rowAll + warp * 512;
    const float4* Bsh4 = (const float4*)Bsh;
    const int rows = NN * 3;
    int nGroups = rows / 4;
    int stride = gridDim.x * 8;
    for (int g = blockIdx.x * 8 + warp; g < nGroups; g += stride) {
        int r0 = g * 4;
#pragma unroll
        for (int i = 0; i < 4; i++)
            ((float4*)row)[i * 32 + lane] = ((const float4*)&g_vec[(r0 + i) * HH])[lane];
        __syncwarp();
        float4 acc[4];
#pragma unroll
        for (int i = 0; i < 4; i++) acc[i] = make_float4(0.f, 0.f, 0.f, 0.f);
#pragma unroll 4
        for (int k = 0; k < HH; k++) {
            float4 b4 = Bsh4[k * 32 + lane];
#pragma unroll
            for (int i = 0; i < 4; i++) fma4(acc[i], row[i * HH + k], b4);
        }
#pragma unroll
        for (int i = 0; i < 4; i++)
            ((float4*)&g_vmix[(r0 + i) * HH])[lane] = acc[i];
        __syncwarp();
    }
}

// ---------------- x += dx @ Wo (N rows) ----------------
__global__ void k_xupdate(const float* __restrict__ Wo) {
    extern __shared__ float sm[];
    float* Bsh = sm;
    float* rowAll = sm + HH * HH;
    int tid = threadIdx.x, warp = tid >> 5, lane = tid & 31;
    for (int i = tid; i < HH * HH; i += blockDim.x) Bsh[i] = Wo[i];
    __syncthreads();
    float* row = rowAll + warp * 512;
    const float4* Bsh4 = (const float4*)Bsh;
    int nGroups = NN / 4;
    int stride = gridDim.x * 8;
    for (int g = blockIdx.x * 8 + warp; g < nGroups; g += stride) {
        int r0 = g * 4;
#pragma unroll
        for (int i = 0; i < 4; i++)
            ((float4*)row)[i * 32 + lane] = ((const float4*)&g_dx[(r0 + i) * HH])[lane];
        __syncwarp();
        float4 acc[4];
#pragma unroll
        for (int i = 0; i < 4; i++) acc[i] = make_float4(0.f, 0.f, 0.f, 0.f);
#pragma unroll 4
        for (int k = 0; k < HH; k++) {
            float4 b4 = Bsh4[k * 32 + lane];
#pragma unroll
            for (int i = 0; i < 4; i++) fma4(acc[i], row[i * HH + k], b4);
        }
#pragma unroll
        for (int i = 0; i < 4; i++) {
            float4 xo = ((const float4*)&g_x[(r0 + i) * HH])[lane];
            xo.x += acc[i].x; xo.y += acc[i].y; xo.z += acc[i].z; xo.w += acc[i].w;
            ((float4*)&g_x[(r0 + i) * HH])[lane] = xo;
        }
        __syncwarp();
    }
}

// ---------------- vmsg scatter into vec ----------------
__global__ void k_vmsg(const int* __restrict__ ei) {
    int warpId = (blockIdx.x * blockDim.x + threadIdx.x) >> 5;
    int lane = threadIdx.x & 31;
    int nw = (gridDim.x * blockDim.x) >> 5;
    for (int e = warpId; e < NE; e += nw) {
        int s = ei[e], t = ei[NE + e];
        float4 dr = ((const float4*)g_dirn)[e];
        float4 ft = ((const float4*)&g_filt[e * HH])[lane];
        float4 ph = ((const float4*)&g_phi[e * HH])[lane];
        float dc[3] = {dr.x, dr.y, dr.z};
#pragma unroll
        for (int c = 0; c < 3; c++) {
            float4 vm = ((const float4*)&g_vmix[(s * 3 + c) * HH])[lane];
            float4 msg;
            msg.x = vm.x * ft.x + ph.x * dc[c];
            msg.y = vm.y * ft.y + ph.y * dc[c];
            msg.z = vm.z * ft.z + ph.z * dc[c];
            msg.w = vm.w * ft.w + ph.w * dc[c];
            atomicAdd4(&g_vec[(t * 3 + c) * HH + lane * 4], msg);
        }
    }
}

// ---------------- vnorm = ||vec @ Wvec2||_c ----------------
#define SMEM_VNORM ((HH * HH + 8 * 384) * 4)
__global__ void k_vnorm(const float* __restrict__ Wvec2) {
    extern __shared__ float sm[];
    float* Bsh = sm;
    float* rowAll = sm + HH * HH;
    int tid = threadIdx.x, warp = tid >> 5, lane = tid & 31;
    for (int i = tid; i < HH * HH; i += blockDim.x) Bsh[i] = Wvec2[i];
    __syncthreads();
    float* row = rowAll + warp * 384;
    const float4* Bsh4 = (const float4*)Bsh;
    int stride = gridDim.x * 8;
    for (int n = blockIdx.x * 8 + warp; n < NN; n += stride) {
#pragma unroll
        for (int c = 0; c < 3; c++)
            ((float4*)row)[c * 32 + lane] = ((const float4*)&g_vec[(n * 3 + c) * HH])[lane];
        __syncwarp();
        float4 a0 = make_float4(0.f, 0.f, 0.f, 0.f);
        float4 a1 = a0, a2 = a0;
#pragma unroll 4
        for (int k = 0; k < HH; k++) {
            float4 b4 = Bsh4[k * 32 + lane];
            fma4(a0, row[k], b4);
            fma4(a1, row[HH + k], b4);
            fma4(a2, row[2 * HH + k], b4);
        }
        float4 vn;
        vn.x = sqrtf(a0.x * a0.x + a1.x * a1.x + a2.x * a2.x + EPSF);
        vn.y = sqrtf(a0.y * a0.y + a1.y * a1.y + a2.y * a2.y + EPSF);
        vn.z = sqrtf(a0.z * a0.z + a1.z * a1.z + a2.z * a2.z + EPSF);
        vn.w = sqrtf(a0.w * a0.w + a1.w * a1.w + a2.w * a2.w + EPSF);
        ((float4*)&g_vnorm[n * HH])[lane] = vn;
        __syncwarp();
    }
}

// ---------------- head: a = silu([x,vnorm]@Wa+ba); out = a@Wb+bb; pool ----------------
#define SMEM_HEAD ((256 * HH + 8320 + 8 * 256) * 4)
__global__ void k_head(const int* __restrict__ batch,
                       const float* __restrict__ Wa, const float* __restrict__ Wb,
                       const float* __restrict__ ba, const float* __restrict__ bb) {
    extern __shared__ float sm[];
    float* WaSh = sm;                 // 256*128
    float* WbSh = WaSh + 256 * HH;    // 128*65 = 8320
    float* rowAll = WbSh + 8320;      // 8*256
    int tid = threadIdx.x, warp = tid >> 5, lane = tid & 31;
    for (int i = tid; i < 256 * HH; i += blockDim.x) WaSh[i] = Wa[i];
    for (int i = tid; i < 128 * 65; i += blockDim.x) WbSh[i] = Wb[i];
    __syncthreads();
    float* row = rowAll + warp * 256;
    const float4* WaSh4 = (const float4*)WaSh;
    int stride = gridDim.x * 8;
    for (int n = blockIdx.x * 8 + warp; n < NN; n += stride) {
        ((float4*)row)[lane] = ((const float4*)&g_x[n * HH])[lane];
        ((float4*)row)[32 + lane] = ((const float4*)&g_vnorm[n * HH])[lane];
        __syncwarp();
        float4 acc = *(const float4*)&ba[lane * 4];
#pragma unroll 4
        for (int k = 0; k < 256; k++) {
            float4 b4 = WaSh4[k * 32 + lane];
            fma4(acc, row[k], b4);
        }
        float4 av = silu4(acc);
        __syncwarp();
        ((float4*)row)[lane] = av;   // row[0..127] now holds a
        __syncwarp();
        int bg = batch[n];
#pragma unroll
        for (int j = 0; j < 3; j++) {
            int col = lane + 32 * j;
            int cc = col < 65 ? col : 64;
            float s = 0.f;
#pragma unroll 4
            for (int k = 0; k < HH; k++) s += row[k] * WbSh[k * 65 + cc];
            if (col < 65) atomicAdd(&g_pooled[bg * 65 + col], s + bb[col]);
        }
        __syncwarp();
    }
}

// ---------------- finalize: mu + clipped log_var ----------------
__global__ void k_finalize(float* __restrict__ out) {
    int i = blockIdx.x * blockDim.x + threadIdx.x;
    if (i < NGR * NLAT) {
        int g = i / NLAT, j = i % NLAT;
        out[i] = g_pooled[g * 65 + j];
    } else if (i < NGR * NLAT + NGR) {
        int g = i - NGR * NLAT;
        float v = g_pooled[g * 65 + 64];
        v = fminf(fmaxf(v, -10.f), 2.f);
        out[i] = v;
    }
}

// ---------------- launch ----------------
extern "C" void kernel_launch(void* const* d_in, const int* in_sizes, int n_in,
                              void* d_out, int out_size) {
    const int*   z    = (const int*)d_in[0];
    const float* pos  = (const float*)d_in[1];
    const int*   batch= (const int*)d_in[2];
    const int*   ei   = (const int*)d_in[3];
    const float* emb  = (const float*)d_in[4];
    const float* Wrbf = (const float*)d_in[5];
    const float* W1   = (const float*)d_in[6];
    const float* Wo   = (const float*)d_in[7];
    const float* Wv   = (const float*)d_in[8];
    /* d_in[9] = Wvec1 (unused by reference) */
    const float* Wvec2= (const float*)d_in[10];
    const float* Wa   = (const float*)d_in[11];
    const float* ba   = (const float*)d_in[12];
    const float* Wb   = (const float*)d_in[13];
    const float* bb   = (const float*)d_in[14];
    float* out = (float*)d_out;

    cudaFuncSetAttribute(k_edge_phi, cudaFuncAttributeMaxDynamicSharedMemorySize, SMEM_EDGEPHI);
    cudaFuncSetAttribute(k_vmix,     cudaFuncAttributeMaxDynamicSharedMemorySize, SMEM_GEMM);
    cudaFuncSetAttribute(k_xupdate,  cudaFuncAttributeMaxDynamicSharedMemorySize, SMEM_GEMM);
    cudaFuncSetAttribute(k_vnorm,    cudaFuncAttributeMaxDynamicSharedMemorySize, SMEM_VNORM);
    cudaFuncSetAttribute(k_head,     cudaFuncAttributeMaxDynamicSharedMemorySize, SMEM_HEAD);

    k_zero_init<<<256, 256>>>();
    k_init_x<<<(NN * HH + 255) / 256, 256>>>(z, emb);
    k_edgeprep<<<(NE + 255) / 256, 256>>>(ei, pos);

    for (int l = 0; l < 2; l++) {
        k_zero_dx<<<256, 256>>>();
        k_edge_phi<<<296, 256, SMEM_EDGEPHI>>>(ei, Wrbf + l * 32 * HH, W1 + l * HH * HH);
        k_vmix<<<296, 256, SMEM_GEMM>>>(Wv + l * HH * HH);
        k_vmsg<<<1024, 256>>>(ei);
        k_xupdate<<<296, 256, SMEM_GEMM>>>(Wo + l * HH * HH);
    }

    k_vnorm<<<296, 256, SMEM_VNORM>>>(Wvec2);
    k_head<<<148, 256, SMEM_HEAD>>>(batch, Wa, Wb, ba, bb);
    k_finalize<<<(NGR * NLAT + NGR + 255) / 256, 256>>>(out);
}

// round 4
// speedup vs baseline: 1.2837x; 1.2837x over previous
#include <cuda_runtime.h>
#include <math.h>

#define NN    10000
#define NE    160000
#define HH    128
#define NRBF  32
#define NLAT  64
#define NGR   128
#define CUTR  5.0f
#define EPSF  1e-8f

typedef unsigned long long u64;

// ---------------- device scratch ----------------
__device__ __align__(16) float g_x[NN * HH];
__device__ __align__(16) float g_dx[NN * HH];
__device__ __align__(16) float g_vec[NN * 3 * HH];
__device__ __align__(16) float g_vmix[NN * 3 * HH];
__device__ __align__(16) float g_vnorm[NN * HH];
__device__ __align__(16) float g_rbf[NE * NRBF];
__device__ __align__(16) float g_dirn[NE * 4];      // (ux,uy,uz,r)
__device__ __align__(16) float g_pooled[NGR * 65];

// ---------------- f32x2 packed helpers (bit-exact fp32) ----------------
__device__ __forceinline__ u64 pack2(float a) {
    u64 r; asm("mov.b64 %0, {%1, %1};" : "=l"(r) : "f"(a)); return r;
}
__device__ __forceinline__ u64 pack_pair(float x, float y) {
    u64 r; asm("mov.b64 %0, {%1, %2};" : "=l"(r) : "f"(x), "f"(y)); return r;
}
__device__ __forceinline__ void ffma2(u64& d, u64 a, u64 b) {
    asm("fma.rn.f32x2 %0, %1, %2, %0;" : "+l"(d) : "l"(a), "l"(b));
}
__device__ __forceinline__ float4 unpack4(u64 lo, u64 hi) {
    float4 v;
    asm("mov.b64 {%0, %1}, %2;" : "=f"(v.x), "=f"(v.y) : "l"(lo));
    asm("mov.b64 {%0, %1}, %2;" : "=f"(v.z), "=f"(v.w) : "l"(hi));
    return v;
}
__device__ __forceinline__ float4 silu4(const float4& v) {
    float4 r;
    r.x = v.x / (1.f + __expf(-v.x));
    r.y = v.y / (1.f + __expf(-v.y));
    r.z = v.z / (1.f + __expf(-v.z));
    r.w = v.w / (1.f + __expf(-v.w));
    return r;
}
__device__ __forceinline__ void atomicAdd4(float* p, const float4& v) {
    atomicAdd((float4*)p, v);
}

// ---------------- init / zero ----------------
__global__ void k_zero_init() {
    int stride = gridDim.x * blockDim.x;
    for (int i = blockIdx.x * blockDim.x + threadIdx.x; i < NN * 3 * HH; i += stride) g_vec[i] = 0.f;
    for (int i = blockIdx.x * blockDim.x + threadIdx.x; i < NGR * 65; i += stride) g_pooled[i] = 0.f;
}
__global__ void k_zero_dx() {
    int stride = gridDim.x * blockDim.x;
    for (int i = blockIdx.x * blockDim.x + threadIdx.x; i < NN * HH; i += stride) g_dx[i] = 0.f;
}
__global__ void k_init_x(const int* __restrict__ z, const float* __restrict__ emb) {
    int stride = gridDim.x * blockDim.x;
    for (int i = blockIdx.x * blockDim.x + threadIdx.x; i < NN * HH; i += stride) {
        int n = i >> 7, h = i & 127;
        g_x[i] = emb[z[n] * HH + h];
    }
}

// ---------------- edge geometry + RBF ----------------
__global__ void k_edgeprep(const int* __restrict__ ei, const float* __restrict__ pos) {
    int e = blockIdx.x * blockDim.x + threadIdx.x;
    if (e >= NE) return;
    int s = ei[e], t = ei[NE + e];
    float dx = pos[t * 3 + 0] - pos[s * 3 + 0];
    float dy = pos[t * 3 + 1] - pos[s * 3 + 1];
    float dz = pos[t * 3 + 2] - pos[s * 3 + 2];
    float r = sqrtf(dx * dx + dy * dy + dz * dz + EPSF);
    float inv = 1.f / r;
    ((float4*)g_dirn)[e] = make_float4(dx * inv, dy * inv, dz * inv, r);

    const float m0 = expf(-CUTR);
    const float step = (1.f - m0) / (NRBF - 1);
    const float bl = (2.f / NRBF) * (1.f - m0);
    const float beta = 1.f / (bl * bl);
    float cutv = (r < CUTR) ? 0.5f * (cosf(3.14159265358979323846f * r / CUTR) + 1.f) : 0.f;
    float er = expf(-r);
#pragma unroll
    for (int i = 0; i < NRBF; i++) {
        float m = m0 + step * (float)i;
        float d = er - m;
        g_rbf[e * NRBF + i] = cutv * expf(-beta * d * d);
    }
}

// ---------------- fused edge kernel: filt + phi + dx scatter + vmsg scatter ----------------
// smem: Wrbf[32x128] + W1[128x128] + rowbuf[8 warps][512]
#define SMEM_EDGE ((32 * HH + HH * HH + 8 * 512) * 4)
__global__ void k_edge_fused(const int* __restrict__ ei,
                             const float* __restrict__ Wrbf,
                             const float* __restrict__ W1,
                             int has_vmix) {
    extern __shared__ float sm[];
    float* WrbfSh = sm;
    float* W1sh = sm + 32 * HH;
    float* rowAll = W1sh + HH * HH;
    int tid = threadIdx.x, warp = tid >> 5, lane = tid & 31;
    for (int i = tid; i < 32 * HH; i += blockDim.x) WrbfSh[i] = Wrbf[i];
    for (int i = tid; i < HH * HH; i += blockDim.x) W1sh[i] = W1[i];
    __syncthreads();
    float* row = rowAll + warp * 512;
    const ulonglong2* W1sh2 = (const ulonglong2*)W1sh;
    const ulonglong2* Wr2 = (const ulonglong2*)WrbfSh;

    int nGroups = NE / 4;
    int stride = gridDim.x * 8;
    for (int g = blockIdx.x * 8 + warp; g < nGroups; g += stride) {
        int e0 = g * 4;
        int srcs[4], dsts[4];
#pragma unroll
        for (int i = 0; i < 4; i++) {
            int e = e0 + i;
            srcs[i] = ei[e]; dsts[i] = ei[NE + e];
            row[i * 32 + lane] = g_rbf[e * 32 + lane];
        }
        __syncwarp();
        // filt = rbf @ Wrbf  (k = 0..31)
        u64 flo[4] = {0, 0, 0, 0}, fhi[4] = {0, 0, 0, 0};
#pragma unroll 4
        for (int k = 0; k < 32; k++) {
            ulonglong2 b = Wr2[k * 32 + lane];
#pragma unroll
            for (int i = 0; i < 4; i++) {
                u64 a = pack2(row[i * 32 + k]);
                ffma2(flo[i], a, b.x); ffma2(fhi[i], a, b.y);
            }
        }
        __syncwarp();
        float4 fv[4];
#pragma unroll
        for (int i = 0; i < 4; i++) {
            fv[i] = unpack4(flo[i], fhi[i]);
            float4 xs = *(const float4*)&g_x[srcs[i] * HH + lane * 4];
            float4 u = make_float4(xs.x * fv[i].x, xs.y * fv[i].y,
                                   xs.z * fv[i].z, xs.w * fv[i].w);
            ((float4*)row)[i * 32 + lane] = u;
        }
        __syncwarp();
        // phi = silu(u @ W1)  (k = 0..127)
        u64 alo[4] = {0, 0, 0, 0}, ahi[4] = {0, 0, 0, 0};
#pragma unroll 4
        for (int k = 0; k < HH; k++) {
            ulonglong2 b = W1sh2[k * 32 + lane];
#pragma unroll
            for (int i = 0; i < 4; i++) {
                u64 a = pack2(row[i * HH + k]);
                ffma2(alo[i], a, b.x); ffma2(ahi[i], a, b.y);
            }
        }
        // epilogue: dx scatter + vmsg scatter
#pragma unroll
        for (int i = 0; i < 4; i++) {
            float4 p = silu4(unpack4(alo[i], ahi[i]));
            atomicAdd4(&g_dx[dsts[i] * HH + lane * 4], p);
            float4 dr = ((const float4*)g_dirn)[e0 + i];
            float dc[3] = {dr.x, dr.y, dr.z};
            if (has_vmix) {
#pragma unroll
                for (int c = 0; c < 3; c++) {
                    float4 vm = ((const float4*)&g_vmix[(srcs[i] * 3 + c) * HH])[lane];
                    float4 msg;
                    msg.x = vm.x * fv[i].x + p.x * dc[c];
                    msg.y = vm.y * fv[i].y + p.y * dc[c];
                    msg.z = vm.z * fv[i].z + p.z * dc[c];
                    msg.w = vm.w * fv[i].w + p.w * dc[c];
                    atomicAdd4(&g_vec[(dsts[i] * 3 + c) * HH + lane * 4], msg);
                }
            } else {
#pragma unroll
                for (int c = 0; c < 3; c++) {
                    float4 msg = make_float4(p.x * dc[c], p.y * dc[c],
                                             p.z * dc[c], p.w * dc[c]);
                    atomicAdd4(&g_vec[(dsts[i] * 3 + c) * HH + lane * 4], msg);
                }
            }
        }
        __syncwarp();
    }
}

// ---------------- vmix = vec @ Wv (N*3 rows) ----------------
#define SMEM_GEMM ((HH * HH + 8 * 512) * 4)
__global__ void k_vmix(const float* __restrict__ Wv) {
    extern __shared__ float sm[];
    float* Bsh = sm;
    float* rowAll = sm + HH * HH;
    int tid = threadIdx.x, warp = tid >> 5, lane = tid & 31;
    for (int i = tid; i < HH * HH; i += blockDim.x) Bsh[i] = Wv[i];
    __syncthreads();
    float* row = rowAll + warp * 512;
    const ulonglong2* Bsh2 = (const ulonglong2*)Bsh;
    const int rows = NN * 3;
    int nGroups = rows / 4;
    int stride = gridDim.x * 8;
    for (int g = blockIdx.x * 8 + warp; g < nGroups; g += stride) {
        int r0 = g * 4;
#pragma unroll
        for (int i = 0; i < 4; i++)
            ((float4*)row)[i * 32 + lane] = ((const float4*)&g_vec[(r0 + i) * HH])[lane];
        __syncwarp();
        u64 alo[4] = {0, 0, 0, 0}, ahi[4] = {0, 0, 0, 0};
#pragma unroll 4
        for (int k = 0; k < HH; k++) {
            ulonglong2 b = Bsh2[k * 32 + lane];
#pragma unroll
            for (int i = 0; i < 4; i++) {
                u64 a = pack2(row[i * HH + k]);
                ffma2(alo[i], a, b.x); ffma2(ahi[i], a, b.y);
            }
        }
#pragma unroll
        for (int i = 0; i < 4; i++)
            ((float4*)&g_vmix[(r0 + i) * HH])[lane] = unpack4(alo[i], ahi[i]);
        __syncwarp();
    }
}

// ---------------- x += dx @ Wo (N rows) ----------------
__global__ void k_xupdate(const float* __restrict__ Wo) {
    extern __shared__ float sm[];
    float* Bsh = sm;
    float* rowAll = sm + HH * HH;
    int tid = threadIdx.x, warp = tid >> 5, lane = tid & 31;
    for (int i = tid; i < HH * HH; i += blockDim.x) Bsh[i] = Wo[i];
    __syncthreads();
    float* row = rowAll + warp * 512;
    const ulonglong2* Bsh2 = (const ulonglong2*)Bsh;
    int nGroups = NN / 4;
    int stride = gridDim.x * 8;
    for (int g = blockIdx.x * 8 + warp; g < nGroups; g += stride) {
        int r0 = g * 4;
#pragma unroll
        for (int i = 0; i < 4; i++)
            ((float4*)row)[i * 32 + lane] = ((const float4*)&g_dx[(r0 + i) * HH])[lane];
        __syncwarp();
        u64 alo[4] = {0, 0, 0, 0}, ahi[4] = {0, 0, 0, 0};
#pragma unroll 4
        for (int k = 0; k < HH; k++) {
            ulonglong2 b = Bsh2[k * 32 + lane];
#pragma unroll
            for (int i = 0; i < 4; i++) {
                u64 a = pack2(row[i * HH + k]);
                ffma2(alo[i], a, b.x); ffma2(ahi[i], a, b.y);
            }
        }
#pragma unroll
        for (int i = 0; i < 4; i++) {
            float4 acc = unpack4(alo[i], ahi[i]);
            float4 xo = ((const float4*)&g_x[(r0 + i) * HH])[lane];
            xo.x += acc.x; xo.y += acc.y; xo.z += acc.z; xo.w += acc.w;
            ((float4*)&g_x[(r0 + i) * HH])[lane] = xo;
        }
        __syncwarp();
    }
}

// ---------------- vnorm = ||vec @ Wvec2||_c ----------------
#define SMEM_VNORM ((HH * HH + 8 * 384) * 4)
__global__ void k_vnorm(const float* __restrict__ Wvec2) {
    extern __shared__ float sm[];
    float* Bsh = sm;
    float* rowAll = sm + HH * HH;
    int tid = threadIdx.x, warp = tid >> 5, lane = tid & 31;
    for (int i = tid; i < HH * HH; i += blockDim.x) Bsh[i] = Wvec2[i];
    __syncthreads();
    float* row = rowAll + warp * 384;
    const ulonglong2* Bsh2 = (const ulonglong2*)Bsh;
    int stride = gridDim.x * 8;
    for (int n = blockIdx.x * 8 + warp; n < NN; n += stride) {
#pragma unroll
        for (int c = 0; c < 3; c++)
            ((float4*)row)[c * 32 + lane] = ((const float4*)&g_vec[(n * 3 + c) * HH])[lane];
        __syncwarp();
        u64 alo[3] = {0, 0, 0}, ahi[3] = {0, 0, 0};
#pragma unroll 4
        for (int k = 0; k < HH; k++) {
            ulonglong2 b = Bsh2[k * 32 + lane];
#pragma unroll
            for (int c = 0; c < 3; c++) {
                u64 a = pack2(row[c * HH + k]);
                ffma2(alo[c], a, b.x); ffma2(ahi[c], a, b.y);
            }
        }
        float4 a0 = unpack4(alo[0], ahi[0]);
        float4 a1 = unpack4(alo[1], ahi[1]);
        float4 a2 = unpack4(alo[2], ahi[2]);
        float4 vn;
        vn.x = sqrtf(a0.x * a0.x + a1.x * a1.x + a2.x * a2.x + EPSF);
        vn.y = sqrtf(a0.y * a0.y + a1.y * a1.y + a2.y * a2.y + EPSF);
        vn.z = sqrtf(a0.z * a0.z + a1.z * a1.z + a2.z * a2.z + EPSF);
        vn.w = sqrtf(a0.w * a0.w + a1.w * a1.w + a2.w * a2.w + EPSF);
        ((float4*)&g_vnorm[n * HH])[lane] = vn;
        __syncwarp();
    }
}

// ---------------- head: a = silu([x,vnorm]@Wa+ba); out = a@Wb+bb; pool ----------------
#define SMEM_HEAD ((256 * HH + 8320 + 8 * 256) * 4)
__global__ void k_head(const int* __restrict__ batch,
                       const float* __restrict__ Wa, const float* __restrict__ Wb,
                       const float* __restrict__ ba, const float* __restrict__ bb) {
    extern __shared__ float sm[];
    float* WaSh = sm;                 // 256*128
    float* WbSh = WaSh + 256 * HH;    // 128*65 = 8320
    float* rowAll = WbSh + 8320;      // 8*256
    int tid = threadIdx.x, warp = tid >> 5, lane = tid & 31;
    for (int i = tid; i < 256 * HH; i += blockDim.x) WaSh[i] = Wa[i];
    for (int i = tid; i < 128 * 65; i += blockDim.x) WbSh[i] = Wb[i];
    __syncthreads();
    float* row = rowAll + warp * 256;
    const ulonglong2* WaSh2 = (const ulonglong2*)WaSh;
    int stride = gridDim.x * 8;
    for (int n = blockIdx.x * 8 + warp; n < NN; n += stride) {
        ((float4*)row)[lane] = ((const float4*)&g_x[n * HH])[lane];
        ((float4*)row)[32 + lane] = ((const float4*)&g_vnorm[n * HH])[lane];
        __syncwarp();
        float4 bav = *(const float4*)&ba[lane * 4];
        u64 acclo = pack_pair(bav.x, bav.y);
        u64 acchi = pack_pair(bav.z, bav.w);
#pragma unroll 4
        for (int k = 0; k < 256; k++) {
            ulonglong2 b = WaSh2[k * 32 + lane];
            u64 a = pack2(row[k]);
            ffma2(acclo, a, b.x); ffma2(acchi, a, b.y);
        }
        float4 av = silu4(unpack4(acclo, acchi));
        __syncwarp();
        ((float4*)row)[lane] = av;   // row[0..127] now holds a
        __syncwarp();
        int bg = batch[n];
#pragma unroll
        for (int j = 0; j < 3; j++) {
            int col = lane + 32 * j;
            int cc = col < 65 ? col : 64;
            float s = 0.f;
#pragma unroll 4
            for (int k = 0; k < HH; k++) s += row[k] * WbSh[k * 65 + cc];
            if (col < 65) atomicAdd(&g_pooled[bg * 65 + col], s + bb[col]);
        }
        __syncwarp();
    }
}

// ---------------- finalize ----------------
__global__ void k_finalize(float* __restrict__ out) {
    int i = blockIdx.x * blockDim.x + threadIdx.x;
    if (i < NGR * NLAT) {
        int g = i / NLAT, j = i % NLAT;
        out[i] = g_pooled[g * 65 + j];
    } else if (i < NGR * NLAT + NGR) {
        int g = i - NGR * NLAT;
        float v = g_pooled[g * 65 + 64];
        v = fminf(fmaxf(v, -10.f), 2.f);
        out[i] = v;
    }
}

// ---------------- launch ----------------
extern "C" void kernel_launch(void* const* d_in, const int* in_sizes, int n_in,
                              void* d_out, int out_size) {
    const int*   z    = (const int*)d_in[0];
    const float* pos  = (const float*)d_in[1];
    const int*   batch= (const int*)d_in[2];
    const int*   ei   = (const int*)d_in[3];
    const float* emb  = (const float*)d_in[4];
    const float* Wrbf = (const float*)d_in[5];
    const float* W1   = (const float*)d_in[6];
    const float* Wo   = (const float*)d_in[7];
    const float* Wv   = (const float*)d_in[8];
    /* d_in[9] = Wvec1 (unused by reference) */
    const float* Wvec2= (const float*)d_in[10];
    const float* Wa   = (const float*)d_in[11];
    const float* ba   = (const float*)d_in[12];
    const float* Wb   = (const float*)d_in[13];
    const float* bb   = (const float*)d_in[14];
    float* out = (float*)d_out;

    cudaFuncSetAttribute(k_edge_fused, cudaFuncAttributeMaxDynamicSharedMemorySize, SMEM_EDGE);
    cudaFuncSetAttribute(k_vmix,       cudaFuncAttributeMaxDynamicSharedMemorySize, SMEM_GEMM);
    cudaFuncSetAttribute(k_xupdate,    cudaFuncAttributeMaxDynamicSharedMemorySize, SMEM_GEMM);
    cudaFuncSetAttribute(k_vnorm,      cudaFuncAttributeMaxDynamicSharedMemorySize, SMEM_VNORM);
    cudaFuncSetAttribute(k_head,       cudaFuncAttributeMaxDynamicSharedMemorySize, SMEM_HEAD);

    k_zero_init<<<256, 256>>>();
    k_init_x<<<(NN * HH + 255) / 256, 256>>>(z, emb);
    k_edgeprep<<<(NE + 255) / 256, 256>>>(ei, pos);

    for (int l = 0; l < 2; l++) {
        k_zero_dx<<<256, 256>>>();
        if (l > 0) k_vmix<<<296, 256, SMEM_GEMM>>>(Wv + l * HH * HH);
        k_edge_fused<<<296, 256, SMEM_EDGE>>>(ei, Wrbf + l * 32 * HH, W1 + l * HH * HH, l > 0 ? 1 : 0);
        k_xupdate<<<296, 256, SMEM_GEMM>>>(Wo + l * HH * HH);
    }

    k_vnorm<<<296, 256, SMEM_VNORM>>>(Wvec2);
    k_head<<<148, 256, SMEM_HEAD>>>(batch, Wa, Wb, ba, bb);
    k_finalize<<<(NGR * NLAT + NGR + 255) / 256, 256>>>(out);
}